// round 5
// baseline (speedup 1.0000x reference)
#include <cuda_runtime.h>
#include <cstdint>

// ---------------- problem constants (from reference) ----------------
#define NPTS_MAX 500000
#define BATCH 2
#define CZd 1
#define CYd 400
#define CXd 352
#define CL (BATCH * CZd * CYd * CXd)   // 281600
#define C_H 64
#define C_IN 11

#define TM 128            // points per block in GEMM2
#define AROW 132          // padded A row stride (floats)

__device__ __constant__ float VXc = 0.2f, VYc = 0.2f, VZc = 4.0f;
__device__ __constant__ float XOFFc = 0.1f;
__device__ __constant__ float YOFFc = -39.9f;
__device__ __constant__ float ZOFFc = -1.0f;

// ---------------- scratch (static device globals; no allocs) ----------------
__device__ float g_pf1[(size_t)C_H * NPTS_MAX];   // [16 g][N][4]
__device__ float g_vmax1[(size_t)CL * C_H];
__device__ float g_vsum[(size_t)CL * 3];
__device__ int   g_cnt[CL];

// ---------------- f32x2 helpers ----------------
__device__ __forceinline__ unsigned long long dup2(float x)
{
    unsigned long long r;
    unsigned int xi = __float_as_uint(x);
    asm("mov.b64 %0, {%1, %1};" : "=l"(r) : "r"(xi));
    return r;
}
__device__ __forceinline__ void ffma2(unsigned long long& acc,
                                      unsigned long long a,
                                      unsigned long long b)
{
    asm("fma.rn.f32x2 %0, %1, %2, %0;" : "+l"(acc) : "l"(a), "l"(b));
}
__device__ __forceinline__ void fadd2(unsigned long long& acc, unsigned long long b)
{
    asm("add.rn.f32x2 %0, %0, %1;" : "+l"(acc) : "l"(b));
}
__device__ __forceinline__ float2 unpack2(unsigned long long v)
{
    unsigned int lo, hi;
    asm("mov.b64 {%0, %1}, %2;" : "=r"(lo), "=r"(hi) : "l"(v));
    return make_float2(__uint_as_float(lo), __uint_as_float(hi));
}

// ---------------- K0: zero scratch + output ----------------
__global__ void k_zero(float* __restrict__ out)
{
    const int total = CL * C_H;
    for (int i = blockIdx.x * blockDim.x + threadIdx.x; i < total;
         i += gridDim.x * blockDim.x) {
        g_vmax1[i] = 0.0f;
        out[i] = 0.0f;
        if (i < CL * 3) g_vsum[i] = 0.0f;
        if (i < CL)     g_cnt[i] = 0;
    }
}

// ---------------- K1: per-voxel count + xyz sum ----------------
__global__ void k_sums(const float* __restrict__ features,
                       const int* __restrict__ coors, int n)
{
    int i = blockIdx.x * blockDim.x + threadIdx.x;
    if (i >= n) return;
    int4 c = reinterpret_cast<const int4*>(coors)[i];
    int idx = ((c.x * CZd + c.y) * CYd + c.z) * CXd + c.w;
    float4 f = reinterpret_cast<const float4*>(features)[i];
    atomicAdd(&g_cnt[idx], 1);
    atomicAdd(&g_vsum[3 * idx + 0], f.x);
    atomicAdd(&g_vsum[3 * idx + 1], f.y);
    atomicAdd(&g_vsum[3 * idx + 2], f.z);
}

// ---------------- K2: feats -> GEMM1 -> relu -> store pf1 + segmax vmax1 ----------------
__global__ void __launch_bounds__(128)
k_pf1(const float* __restrict__ features, const int* __restrict__ coors,
      const float* __restrict__ W1, const float* __restrict__ scale1,
      const float* __restrict__ shift1, int n)
{
    __shared__ float sW1[C_IN][C_H];
    __shared__ float sSc[C_H], sSh[C_H];
    for (int t = threadIdx.x; t < C_IN * C_H; t += blockDim.x)
        sW1[t / C_H][t % C_H] = W1[t];
    if (threadIdx.x < C_H) {
        sSc[threadIdx.x] = scale1[threadIdx.x];
        sSh[threadIdx.x] = shift1[threadIdx.x];
    }
    __syncthreads();

    int i = blockIdx.x * blockDim.x + threadIdx.x;
    if (i >= n) return;

    int4 c = reinterpret_cast<const int4*>(coors)[i];
    int idx = ((c.x * CZd + c.y) * CYd + c.z) * CXd + c.w;

    const float4 f = reinterpret_cast<const float4*>(features)[i];

    float inv = 1.0f / fmaxf((float)g_cnt[idx], 1.0f);
    float mx = g_vsum[3 * idx + 0] * inv;
    float my = g_vsum[3 * idx + 1] * inv;
    float mz = g_vsum[3 * idx + 2] * inv;

    float feats[C_IN];
    feats[0] = f.x; feats[1] = f.y; feats[2] = f.z; feats[3] = f.w;
    feats[4] = f.x - mx; feats[5] = f.y - my; feats[6] = f.z - mz;
    feats[7] = f.x - ((float)c.w * VXc + XOFFc);
    feats[8] = f.y - ((float)c.z * VYc + YOFFc);
    feats[9] = f.z - ((float)c.y * VZc + ZOFFc);
    feats[10] = sqrtf(f.x * f.x + f.y * f.y + f.z * f.z);

    float acc[C_H];
#pragma unroll
    for (int j = 0; j < C_H; j++) acc[j] = 0.0f;
#pragma unroll
    for (int k = 0; k < C_IN; k++) {
        float fk = feats[k];
#pragma unroll
        for (int j = 0; j < C_H; j++)
            acc[j] = fmaf(fk, sW1[k][j], acc[j]);
    }

    const size_t base = (size_t)idx * C_H;
    float4* pf1_4 = reinterpret_cast<float4*>(g_pf1);

#pragma unroll 1
    for (int g = 0; g < 16; g++) {
        int j = 4 * g;
        float4 r;
        r.x = fmaxf(fmaf(acc[j + 0], sSc[j + 0], sSh[j + 0]), 0.0f);
        r.y = fmaxf(fmaf(acc[j + 1], sSc[j + 1], sSh[j + 1]), 0.0f);
        r.z = fmaxf(fmaf(acc[j + 2], sSc[j + 2], sSh[j + 2]), 0.0f);
        r.w = fmaxf(fmaf(acc[j + 3], sSc[j + 3], sSh[j + 3]), 0.0f);
        pf1_4[(size_t)g * n + i] = r;
        if (r.x > 0.0f) atomicMax((int*)&g_vmax1[base + j + 0], __float_as_int(r.x));
        if (r.y > 0.0f) atomicMax((int*)&g_vmax1[base + j + 1], __float_as_int(r.y));
        if (r.z > 0.0f) atomicMax((int*)&g_vmax1[base + j + 2], __float_as_int(r.z));
        if (r.w > 0.0f) atomicMax((int*)&g_vmax1[base + j + 3], __float_as_int(r.w));
    }
}

// ---------------- K3: smem-tiled GEMM2, K-split, conflict-free B mapping ----------------
// 256 threads. Tile M=128 x N=64 x K=128. Thread-tile: 8 points x 8 cols,
// cols = {4tx..4tx+3} U {32+4tx..32+4tx+3}  (two 16B chunks, bank-conflict-free).
__global__ void __launch_bounds__(256, 2)
k_pf2(const int* __restrict__ coors, const float* __restrict__ W2,
      const float* __restrict__ scale2, const float* __restrict__ shift2,
      float* __restrict__ out, int n)
{
    extern __shared__ float sm[];
    float* sA  = sm;                        // [128 k][AROW]
    float* sB  = sm + 128 * AROW;           // [128 k][64]
    float* sSc = sB + 128 * C_H;
    float* sSh = sSc + C_H;
    int*   sIdx = (int*)(sSh + C_H);        // 128

    const int tid = threadIdx.x;
    const int t   = tid & 127;
    const int kh  = tid >> 7;               // 0 or 1
    const int bstart = blockIdx.x * TM;
    const int i = bstart + t;

    // ---- stage W2 + scale/shift ----
    {
        const float4* w4 = reinterpret_cast<const float4*>(W2);
        float4* b4 = reinterpret_cast<float4*>(sB);
        for (int v = tid; v < 2 * C_H * C_H / 4; v += 256) b4[v] = w4[v];
        if (tid < C_H) { sSc[tid] = scale2[tid]; sSh[tid] = shift2[tid]; }
    }

    // ---- stage voxel idx (half 0) ----
    if (kh == 0) {
        int myIdx = -1;
        if (i < n) {
            int4 c = reinterpret_cast<const int4*>(coors)[i];
            myIdx = ((c.x * CZd + c.y) * CYd + c.z) * CXd + c.w;
        }
        sIdx[t] = myIdx;
    }
    __syncthreads();

    // ---- stage A: half 0 loads pf1 (k 0..63), half 1 gathers vmax1 (k 64..127) ----
    if (kh == 0) {
        const float4* pf1_4 = reinterpret_cast<const float4*>(g_pf1);
#pragma unroll 1
        for (int g = 0; g < 16; g++) {
            float4 v = make_float4(0.f, 0.f, 0.f, 0.f);
            if (i < n) v = pf1_4[(size_t)g * n + i];
            int k0 = 4 * g;
            sA[(k0 + 0) * AROW + t] = v.x;
            sA[(k0 + 1) * AROW + t] = v.y;
            sA[(k0 + 2) * AROW + t] = v.z;
            sA[(k0 + 3) * AROW + t] = v.w;
        }
    } else {
        const int myIdx = sIdx[t];
        const float4* vmax_4 = reinterpret_cast<const float4*>(g_vmax1);
        const size_t vb = (size_t)(myIdx < 0 ? 0 : myIdx) * 16;
#pragma unroll 1
        for (int g = 0; g < 16; g++) {
            float4 v = make_float4(0.f, 0.f, 0.f, 0.f);
            if (myIdx >= 0) v = vmax_4[vb + g];
            int k0 = C_H + 4 * g;
            sA[(k0 + 0) * AROW + t] = v.x;
            sA[(k0 + 1) * AROW + t] = v.y;
            sA[(k0 + 2) * AROW + t] = v.z;
            sA[(k0 + 3) * AROW + t] = v.w;
        }
    }
    __syncthreads();

    // ---- mainloop over this half's K range ----
    const int tx = t & 7;
    const int ty = t >> 3;

    unsigned long long acc[32];
#pragma unroll
    for (int q = 0; q < 32; q++) acc[q] = 0ull;

    const float* aBase = sA + ty * 8;
    const float* bBase0 = sB + tx * 4;        // chunk tx     (cols 4tx..4tx+3)
    const float* bBase1 = sB + 32 + tx * 4;   // chunk tx+8   (cols 32+4tx..+3)
    const int kbeg = kh * 64;

#pragma unroll 4
    for (int kk = 0; kk < 64; kk++) {
        int k = kbeg + kk;
        float4 a0 = *reinterpret_cast<const float4*>(aBase + k * AROW);
        float4 a1 = *reinterpret_cast<const float4*>(aBase + k * AROW + 4);
        ulonglong2 b01 = *reinterpret_cast<const ulonglong2*>(bBase0 + k * C_H);
        ulonglong2 b23 = *reinterpret_cast<const ulonglong2*>(bBase1 + k * C_H);
        unsigned long long bb[4] = { b01.x, b01.y, b23.x, b23.y };
        float av[8] = { a0.x, a0.y, a0.z, a0.w, a1.x, a1.y, a1.z, a1.w };
#pragma unroll
        for (int mi = 0; mi < 8; mi++) {
            unsigned long long am = dup2(av[mi]);
#pragma unroll
            for (int q = 0; q < 4; q++) ffma2(acc[mi * 4 + q], am, bb[q]);
        }
    }

    // ---- combine halves (reuse sA region as u64 buffer) ----
    __syncthreads();
    unsigned long long* sRed = (unsigned long long*)sA;   // [32][128]
    if (kh == 1) {
#pragma unroll
        for (int q = 0; q < 32; q++) sRed[q * 128 + t] = acc[q];
    }
    __syncthreads();
    if (kh == 1) return;

#pragma unroll
    for (int q = 0; q < 32; q++) fadd2(acc[q], sRed[q * 128 + t]);

    // ---- epilogue: affine + relu + atomic segmax ----
    // cols: q=0 -> {4tx, 4tx+1}, q=1 -> {4tx+2, 4tx+3},
    //       q=2 -> {32+4tx, 32+4tx+1}, q=3 -> {32+4tx+2, 32+4tx+3}
    float scv[8], shv[8];
#pragma unroll
    for (int j = 0; j < 4; j++) {
        scv[j] = sSc[4 * tx + j];      shv[j] = sSh[4 * tx + j];
        scv[4 + j] = sSc[32 + 4 * tx + j]; shv[4 + j] = sSh[32 + 4 * tx + j];
    }

#pragma unroll 1
    for (int mi = 0; mi < 8; mi++) {
        int p = ty * 8 + mi;
        int vidx = sIdx[p];
        if (vidx < 0) continue;
        float* ob0 = out + (size_t)vidx * C_H + 4 * tx;
        float* ob1 = ob0 + 32;
#pragma unroll
        for (int q = 0; q < 2; q++) {
            float2 a = unpack2(acc[mi * 4 + q]);
            float v0 = fmaxf(fmaf(a.x, scv[2 * q + 0], shv[2 * q + 0]), 0.0f);
            float v1 = fmaxf(fmaf(a.y, scv[2 * q + 1], shv[2 * q + 1]), 0.0f);
            if (v0 > 0.0f) atomicMax((int*)&ob0[2 * q + 0], __float_as_int(v0));
            if (v1 > 0.0f) atomicMax((int*)&ob0[2 * q + 1], __float_as_int(v1));
        }
#pragma unroll
        for (int q = 0; q < 2; q++) {
            float2 a = unpack2(acc[mi * 4 + 2 + q]);
            float v0 = fmaxf(fmaf(a.x, scv[4 + 2 * q + 0], shv[4 + 2 * q + 0]), 0.0f);
            float v1 = fmaxf(fmaf(a.y, scv[4 + 2 * q + 1], shv[4 + 2 * q + 1]), 0.0f);
            if (v0 > 0.0f) atomicMax((int*)&ob1[2 * q + 0], __float_as_int(v0));
            if (v1 > 0.0f) atomicMax((int*)&ob1[2 * q + 1], __float_as_int(v1));
        }
    }
}

// ---------------- launch ----------------
extern "C" void kernel_launch(void* const* d_in, const int* in_sizes, int n_in,
                              void* d_out, int out_size)
{
    const float* features = (const float*)d_in[0];
    const int*   coors    = (const int*)d_in[1];
    const float* W1       = (const float*)d_in[2];
    const float* scale1   = (const float*)d_in[3];
    const float* shift1   = (const float*)d_in[4];
    const float* W2       = (const float*)d_in[5];
    const float* scale2   = (const float*)d_in[6];
    const float* shift2   = (const float*)d_in[7];
    float* out = (float*)d_out;

    int n = in_sizes[0] / 4;   // N points

    const int smem_pf2 = (128 * AROW + 128 * C_H + 2 * C_H) * 4 + 128 * 4;
    static bool attr_set = false;
    if (!attr_set) {
        cudaFuncSetAttribute(k_pf2, cudaFuncAttributeMaxDynamicSharedMemorySize,
                             smem_pf2);
        attr_set = true;
    }

    k_zero<<<592, 256>>>(out);
    k_sums<<<(n + 255) / 256, 256>>>(features, coors, n);
    k_pf1<<<(n + 127) / 128, 128>>>(features, coors, W1, scale1, shift1, n);
    k_pf2<<<(n + TM - 1) / TM, 256, smem_pf2>>>(coors, W2, scale2, shift2, out, n);
}

// round 6
// speedup vs baseline: 1.4431x; 1.4431x over previous
#include <cuda_runtime.h>
#include <cstdint>

// ---------------- problem constants ----------------
#define NPTS_MAX 500000
#define BATCH 2
#define CZd 1
#define CYd 400
#define CXd 352
#define CL (BATCH * CZd * CYd * CXd)   // 281600
#define C_H 64
#define C_IN 11
#define AROW 132

__device__ __constant__ float VXc = 0.2f, VYc = 0.2f, VZc = 4.0f;
__device__ __constant__ float XOFFc = 0.1f;
__device__ __constant__ float YOFFc = -39.9f;
__device__ __constant__ float ZOFFc = -1.0f;

// ---------------- scratch ----------------
__device__ float g_ctr1[(size_t)C_H * NPTS_MAX];   // [N][64] contrib1 (row-major)
__device__ float g_ctr2[(size_t)CL * C_H];         // [CL][64] contrib2
__device__ float g_vmax1[(size_t)CL * C_H];
__device__ float g_vsum[(size_t)CL * 3];
__device__ int   g_cnt[CL];

// ---------------- f32x2 helpers ----------------
__device__ __forceinline__ unsigned long long dup2(float x)
{
    unsigned long long r;
    unsigned int xi = __float_as_uint(x);
    asm("mov.b64 %0, {%1, %1};" : "=l"(r) : "r"(xi));
    return r;
}
__device__ __forceinline__ void ffma2(unsigned long long& acc,
                                      unsigned long long a, unsigned long long b)
{
    asm("fma.rn.f32x2 %0, %1, %2, %0;" : "+l"(acc) : "l"(a), "l"(b));
}
__device__ __forceinline__ float2 unpack2(unsigned long long v)
{
    unsigned int lo, hi;
    asm("mov.b64 {%0, %1}, %2;" : "=r"(lo), "=r"(hi) : "l"(v));
    return make_float2(__uint_as_float(lo), __uint_as_float(hi));
}

// ---------------- shared 8x8-tile GEMM mainloop (K=64) ----------------
// sA: [64][AROW] (k-major points), sB: [64][64] (k-major cols)
// thread (tx 0..7, ty 0..15): points ty*8..+7, cols {4tx..4tx+3} U {32+4tx..+3}
__device__ __forceinline__ void gemm64_tile(const float* __restrict__ sA,
                                            const float* __restrict__ sB,
                                            int tx, int ty,
                                            unsigned long long acc[32])
{
    const float* aBase  = sA + ty * 8;
    const float* bBase0 = sB + tx * 4;
    const float* bBase1 = sB + 32 + tx * 4;
#pragma unroll 4
    for (int k = 0; k < 64; k++) {
        float4 a0 = *reinterpret_cast<const float4*>(aBase + k * AROW);
        float4 a1 = *reinterpret_cast<const float4*>(aBase + k * AROW + 4);
        ulonglong2 b01 = *reinterpret_cast<const ulonglong2*>(bBase0 + k * C_H);
        ulonglong2 b23 = *reinterpret_cast<const ulonglong2*>(bBase1 + k * C_H);
        unsigned long long bb[4] = { b01.x, b01.y, b23.x, b23.y };
        float av[8] = { a0.x, a0.y, a0.z, a0.w, a1.x, a1.y, a1.z, a1.w };
#pragma unroll
        for (int mi = 0; mi < 8; mi++) {
            unsigned long long am = dup2(av[mi]);
#pragma unroll
            for (int q = 0; q < 4; q++) ffma2(acc[mi * 4 + q], am, bb[q]);
        }
    }
}

// store one thread's 8x8 tile to a row-major [rows][64] buffer
__device__ __forceinline__ void store_tile_rowmajor(float* __restrict__ dst,
                                                    size_t row0, int nrows_valid,
                                                    int tx, int ty,
                                                    const unsigned long long acc[32])
{
#pragma unroll
    for (int mi = 0; mi < 8; mi++) {
        int p = ty * 8 + mi;
        if (p >= nrows_valid) continue;
        float* r = dst + (row0 + p) * C_H;
        float2 a0 = unpack2(acc[mi * 4 + 0]);
        float2 a1 = unpack2(acc[mi * 4 + 1]);
        float2 a2 = unpack2(acc[mi * 4 + 2]);
        float2 a3 = unpack2(acc[mi * 4 + 3]);
        *reinterpret_cast<float4*>(r + 4 * tx)      = make_float4(a0.x, a0.y, a1.x, a1.y);
        *reinterpret_cast<float4*>(r + 32 + 4 * tx) = make_float4(a2.x, a2.y, a3.x, a3.y);
    }
}

// ---------------- K0: zero ----------------
__global__ void k_zero(float* __restrict__ out)
{
    const int total = CL * C_H;
    for (int i = blockIdx.x * blockDim.x + threadIdx.x; i < total;
         i += gridDim.x * blockDim.x) {
        g_vmax1[i] = 0.0f;
        out[i] = 0.0f;
        if (i < CL * 3) g_vsum[i] = 0.0f;
        if (i < CL)     g_cnt[i] = 0;
    }
}

// ---------------- K1: per-voxel count + xyz sum ----------------
__global__ void k_sums(const float* __restrict__ features,
                       const int* __restrict__ coors, int n)
{
    int i = blockIdx.x * blockDim.x + threadIdx.x;
    if (i >= n) return;
    int4 c = reinterpret_cast<const int4*>(coors)[i];
    int idx = ((c.x * CZd + c.y) * CYd + c.z) * CXd + c.w;
    float4 f = reinterpret_cast<const float4*>(features)[i];
    atomicAdd(&g_cnt[idx], 1);
    atomicAdd(&g_vsum[3 * idx + 0], f.x);
    atomicAdd(&g_vsum[3 * idx + 1], f.y);
    atomicAdd(&g_vsum[3 * idx + 2], f.z);
}

// ---------------- K2: fused pf1 + vmax atomics + contrib1 = pf1 @ W2a ----------------
__global__ void __launch_bounds__(128)
k_fused1(const float* __restrict__ features, const int* __restrict__ coors,
         const float* __restrict__ W1, const float* __restrict__ scale1,
         const float* __restrict__ shift1, const float* __restrict__ W2, int n)
{
    extern __shared__ float sm[];
    float* sA  = sm;                       // [64][AROW]
    float* sB  = sm + 64 * AROW;           // [64][64] = W2 rows 0..63
    float* sW1 = sB + 64 * C_H;            // [11][64]
    float* sSc = sW1 + C_IN * C_H;
    float* sSh = sSc + C_H;

    const int t = threadIdx.x;
    const int bstart = blockIdx.x * 128;
    const int i = bstart + t;

    // stage W2a, W1, scale1/shift1
    {
        const float4* w4 = reinterpret_cast<const float4*>(W2);
        float4* b4 = reinterpret_cast<float4*>(sB);
        for (int v = t; v < 64 * C_H / 4; v += 128) b4[v] = w4[v];
        for (int v = t; v < C_IN * C_H; v += 128) sW1[v] = W1[v];
        if (t < C_H) { sSc[t] = scale1[t]; sSh[t] = shift1[t]; }
    }
    __syncthreads();

    // ---- phase 1: per-thread GEMM1 -> relu -> pf ----
    float pf[C_H];
    int idx = -1;
    if (i < n) {
        int4 c = reinterpret_cast<const int4*>(coors)[i];
        idx = ((c.x * CZd + c.y) * CYd + c.z) * CXd + c.w;
        float4 f = reinterpret_cast<const float4*>(features)[i];

        float inv = 1.0f / fmaxf((float)g_cnt[idx], 1.0f);
        float mx = g_vsum[3 * idx + 0] * inv;
        float my = g_vsum[3 * idx + 1] * inv;
        float mz = g_vsum[3 * idx + 2] * inv;

        float feats[C_IN];
        feats[0] = f.x; feats[1] = f.y; feats[2] = f.z; feats[3] = f.w;
        feats[4] = f.x - mx; feats[5] = f.y - my; feats[6] = f.z - mz;
        feats[7] = f.x - ((float)c.w * VXc + XOFFc);
        feats[8] = f.y - ((float)c.z * VYc + YOFFc);
        feats[9] = f.z - ((float)c.y * VZc + ZOFFc);
        feats[10] = sqrtf(f.x * f.x + f.y * f.y + f.z * f.z);

        float accp[C_H];
#pragma unroll
        for (int j = 0; j < C_H; j++) accp[j] = 0.0f;
#pragma unroll
        for (int k = 0; k < C_IN; k++) {
            float fk = feats[k];
#pragma unroll
            for (int j = 0; j < C_H; j++)
                accp[j] = fmaf(fk, sW1[k * C_H + j], accp[j]);
        }
#pragma unroll
        for (int j = 0; j < C_H; j++)
            pf[j] = fmaxf(fmaf(accp[j], sSc[j], sSh[j]), 0.0f);
    } else {
#pragma unroll
        for (int j = 0; j < C_H; j++) pf[j] = 0.0f;
    }

    // STS pf -> sA (k-major), + vmax1 atomics
#pragma unroll
    for (int k = 0; k < C_H; k++) sA[k * AROW + t] = pf[k];
    if (idx >= 0) {
        float* vb = &g_vmax1[(size_t)idx * C_H];
#pragma unroll
        for (int j = 0; j < C_H; j++)
            if (pf[j] > 0.0f) atomicMax((int*)&vb[j], __float_as_int(pf[j]));
    }
    __syncthreads();

    // ---- phase 2: tiled GEMM contrib1 = pf_tile @ W2a ----
    const int tx = t & 7;
    const int ty = t >> 3;
    unsigned long long acc[32];
#pragma unroll
    for (int q = 0; q < 32; q++) acc[q] = 0ull;

    gemm64_tile(sA, sB, tx, ty, acc);

    int nvalid = n - bstart;
    if (nvalid > 128) nvalid = 128;
    store_tile_rowmajor(g_ctr1, (size_t)bstart, nvalid, tx, ty, acc);
}

// ---------------- K3: contrib2 = vmax1 @ W2b (per voxel) ----------------
__global__ void __launch_bounds__(128)
k_ctr2(const float* __restrict__ W2)
{
    extern __shared__ float sm[];
    float* sA = sm;                    // [64][AROW]
    float* sB = sm + 64 * AROW;        // [64][64] = W2 rows 64..127

    const int t = threadIdx.x;
    const size_t v0 = (size_t)blockIdx.x * 128;

    {
        const float4* w4 = reinterpret_cast<const float4*>(W2 + C_H * C_H);
        float4* b4 = reinterpret_cast<float4*>(sB);
        for (int q = t; q < 64 * C_H / 4; q += 128) b4[q] = w4[q];
    }

    // stage vmax1 rows (one row per thread) -> sA k-major
    const float4* vm4 = reinterpret_cast<const float4*>(g_vmax1 + (v0 + t) * C_H);
#pragma unroll
    for (int g = 0; g < 16; g++) {
        float4 x = vm4[g];
        int k0 = 4 * g;
        sA[(k0 + 0) * AROW + t] = x.x;
        sA[(k0 + 1) * AROW + t] = x.y;
        sA[(k0 + 2) * AROW + t] = x.z;
        sA[(k0 + 3) * AROW + t] = x.w;
    }
    __syncthreads();

    const int tx = t & 7;
    const int ty = t >> 3;
    unsigned long long acc[32];
#pragma unroll
    for (int q = 0; q < 32; q++) acc[q] = 0ull;

    gemm64_tile(sA, sB, tx, ty, acc);
    store_tile_rowmajor(g_ctr2, v0, 128, tx, ty, acc);   // CL = 128*2200 exact
}

// ---------------- K4: final combine + affine + relu + segmax ----------------
__global__ void __launch_bounds__(256)
k_final(const int* __restrict__ coors, const float* __restrict__ scale2,
        const float* __restrict__ shift2, float* __restrict__ out, int n)
{
    __shared__ float sSc[C_H], sSh[C_H];
    if (threadIdx.x < C_H) {
        sSc[threadIdx.x] = scale2[threadIdx.x];
        sSh[threadIdx.x] = shift2[threadIdx.x];
    }
    __syncthreads();

    int gid = blockIdx.x * 256 + threadIdx.x;
    int i = gid >> 2;
    int q = gid & 3;          // 16-col slice
    if (i >= n) return;

    int4 c = reinterpret_cast<const int4*>(coors)[i];
    int idx = ((c.x * CZd + c.y) * CYd + c.z) * CXd + c.w;

    const float4* c1 = reinterpret_cast<const float4*>(g_ctr1 + (size_t)i * C_H) + q * 4;
    const float4* c2 = reinterpret_cast<const float4*>(g_ctr2 + (size_t)idx * C_H) + q * 4;
    float* ob = out + (size_t)idx * C_H + q * 16;

#pragma unroll
    for (int r = 0; r < 4; r++) {
        float4 a = c1[r];
        float4 b = c2[r];
        int j = q * 16 + 4 * r;
        float v0 = fmaxf(fmaf(a.x + b.x, sSc[j + 0], sSh[j + 0]), 0.0f);
        float v1 = fmaxf(fmaf(a.y + b.y, sSc[j + 1], sSh[j + 1]), 0.0f);
        float v2 = fmaxf(fmaf(a.z + b.z, sSc[j + 2], sSh[j + 2]), 0.0f);
        float v3 = fmaxf(fmaf(a.w + b.w, sSc[j + 3], sSh[j + 3]), 0.0f);
        if (v0 > 0.0f) atomicMax((int*)&ob[4 * r + 0], __float_as_int(v0));
        if (v1 > 0.0f) atomicMax((int*)&ob[4 * r + 1], __float_as_int(v1));
        if (v2 > 0.0f) atomicMax((int*)&ob[4 * r + 2], __float_as_int(v2));
        if (v3 > 0.0f) atomicMax((int*)&ob[4 * r + 3], __float_as_int(v3));
    }
}

// ---------------- launch ----------------
extern "C" void kernel_launch(void* const* d_in, const int* in_sizes, int n_in,
                              void* d_out, int out_size)
{
    const float* features = (const float*)d_in[0];
    const int*   coors    = (const int*)d_in[1];
    const float* W1       = (const float*)d_in[2];
    const float* scale1   = (const float*)d_in[3];
    const float* shift1   = (const float*)d_in[4];
    const float* W2       = (const float*)d_in[5];
    const float* scale2   = (const float*)d_in[6];
    const float* shift2   = (const float*)d_in[7];
    float* out = (float*)d_out;

    int n = in_sizes[0] / 4;

    const int smemA = (64 * AROW + 64 * C_H + C_IN * C_H + 2 * C_H) * 4;  // ~53.3KB
    const int smemB = (64 * AROW + 64 * C_H) * 4;                         // ~50.2KB
    static bool attr_set = false;
    if (!attr_set) {
        cudaFuncSetAttribute(k_fused1, cudaFuncAttributeMaxDynamicSharedMemorySize, smemA);
        cudaFuncSetAttribute(k_ctr2,   cudaFuncAttributeMaxDynamicSharedMemorySize, smemB);
        attr_set = true;
    }

    k_zero<<<592, 256>>>(out);
    k_sums<<<(n + 255) / 256, 256>>>(features, coors, n);
    k_fused1<<<(n + 127) / 128, 128, smemA>>>(features, coors, W1, scale1, shift1, W2, n);
    k_ctr2<<<CL / 128, 128, smemB>>>(W2);
    k_final<<<(4 * n + 255) / 256, 256>>>(coors, scale2, shift2, out, n);
}

// round 7
// speedup vs baseline: 1.4688x; 1.0178x over previous
#include <cuda_runtime.h>
#include <cstdint>

// ---------------- problem constants ----------------
#define NPTS_MAX 500000
#define BATCH 2
#define CZd 1
#define CYd 400
#define CXd 352
#define CL (BATCH * CZd * CYd * CXd)   // 281600
#define C_H 64
#define C_IN 11
#define AROW 132

__device__ __constant__ float VXc = 0.2f, VYc = 0.2f, VZc = 4.0f;
__device__ __constant__ float XOFFc = 0.1f;
__device__ __constant__ float YOFFc = -39.9f;
__device__ __constant__ float ZOFFc = -1.0f;

// ---------------- scratch ----------------
__device__ float g_ctr1[(size_t)C_H * NPTS_MAX];   // [N][64]  c1' = pf1 @ (W2a*sc2)
__device__ float g_ctr2[(size_t)CL * C_H];         // [CL][64] c2' = vmax @ (W2b*sc2) + sh2
__device__ float g_vmax1[(size_t)CL * C_H];
__device__ float g_vsum[(size_t)CL * 3];
__device__ int   g_cnt[CL];

// ---------------- f32x2 helpers ----------------
__device__ __forceinline__ unsigned long long dup2(float x)
{
    unsigned long long r;
    unsigned int xi = __float_as_uint(x);
    asm("mov.b64 %0, {%1, %1};" : "=l"(r) : "r"(xi));
    return r;
}
__device__ __forceinline__ void ffma2(unsigned long long& acc,
                                      unsigned long long a, unsigned long long b)
{
    asm("fma.rn.f32x2 %0, %1, %2, %0;" : "+l"(acc) : "l"(a), "l"(b));
}
__device__ __forceinline__ float2 unpack2(unsigned long long v)
{
    unsigned int lo, hi;
    asm("mov.b64 {%0, %1}, %2;" : "=r"(lo), "=r"(hi) : "l"(v));
    return make_float2(__uint_as_float(lo), __uint_as_float(hi));
}

// col owned by (tx, cc): cc<4 -> 4tx+cc ; cc>=4 -> 32+4tx+cc-4
__device__ __forceinline__ int colof(int tx, int cc)
{
    return (cc < 4) ? (4 * tx + cc) : (32 + 4 * tx + cc - 4);
}

// one k-step of the 8x8 tile FFMA2 body
__device__ __forceinline__ void tile_fma(const float4 a0, const float4 a1,
                                         const unsigned long long bb[4],
                                         unsigned long long acc[32])
{
    float av[8] = { a0.x, a0.y, a0.z, a0.w, a1.x, a1.y, a1.z, a1.w };
#pragma unroll
    for (int mi = 0; mi < 8; mi++) {
        unsigned long long am = dup2(av[mi]);
#pragma unroll
        for (int q = 0; q < 4; q++) ffma2(acc[mi * 4 + q], am, bb[q]);
    }
}

// ---------------- K0: zero ----------------
__global__ void k_zero(float* __restrict__ out)
{
    const int total = CL * C_H;
    for (int i = blockIdx.x * blockDim.x + threadIdx.x; i < total;
         i += gridDim.x * blockDim.x) {
        g_vmax1[i] = 0.0f;
        out[i] = 0.0f;
        if (i < CL * 3) g_vsum[i] = 0.0f;
        if (i < CL)     g_cnt[i] = 0;
    }
}

// ---------------- K1: per-voxel count + xyz sum ----------------
__global__ void k_sums(const float* __restrict__ features,
                       const int* __restrict__ coors, int n)
{
    int i = blockIdx.x * blockDim.x + threadIdx.x;
    if (i >= n) return;
    int4 c = reinterpret_cast<const int4*>(coors)[i];
    int idx = ((c.x * CZd + c.y) * CYd + c.z) * CXd + c.w;
    float4 f = reinterpret_cast<const float4*>(features)[i];
    atomicAdd(&g_cnt[idx], 1);
    atomicAdd(&g_vsum[3 * idx + 0], f.x);
    atomicAdd(&g_vsum[3 * idx + 1], f.y);
    atomicAdd(&g_vsum[3 * idx + 2], f.z);
}

// ---------------- K2: fused (tiled GEMM1 -> pf) + vmax atomics + (tiled GEMM2a -> c1') ----------------
__global__ void __launch_bounds__(128, 4)
k_fused1(const float* __restrict__ features, const int* __restrict__ coors,
         const float* __restrict__ W1, const float* __restrict__ scale1,
         const float* __restrict__ shift1, const float* __restrict__ W2,
         const float* __restrict__ scale2, int n)
{
    extern __shared__ float sm[];
    float* sA   = sm;                      // [64][128] swizzled pf / aliased feats [11][128]
    float* sB   = sA + 64 * 128;           // [64][64]  W2a * scale2
    float* sW1b = sB + 64 * C_H;           // [11][64]
    float* sSc  = sW1b + C_IN * C_H;       // scale1
    float* sSh  = sSc + C_H;               // shift1
    int*   sIdx = (int*)(sSh + C_H);       // 128

    const int t = threadIdx.x;
    const int tx = t & 7;
    const int ty = t >> 3;
    const int bstart = blockIdx.x * 128;
    const int i = bstart + t;

    // ---- stage weights (fold scale2 into W2a) ----
    for (int v = t; v < 64 * C_H; v += 128) sB[v] = W2[v] * scale2[v & 63];
    for (int v = t; v < C_IN * C_H; v += 128) sW1b[v] = W1[v];
    if (t < C_H) { sSc[t] = scale1[t]; sSh[t] = shift1[t]; }

    // ---- per-thread feats -> staged plainly into sA[k][t] (k<11) ----
    int idx = -1;
    {
        float feats[C_IN];
        if (i < n) {
            int4 c = reinterpret_cast<const int4*>(coors)[i];
            idx = ((c.x * CZd + c.y) * CYd + c.z) * CXd + c.w;
            float4 f = reinterpret_cast<const float4*>(features)[i];
            float inv = 1.0f / fmaxf((float)g_cnt[idx], 1.0f);
            float mx = g_vsum[3 * idx + 0] * inv;
            float my = g_vsum[3 * idx + 1] * inv;
            float mz = g_vsum[3 * idx + 2] * inv;
            feats[0] = f.x; feats[1] = f.y; feats[2] = f.z; feats[3] = f.w;
            feats[4] = f.x - mx; feats[5] = f.y - my; feats[6] = f.z - mz;
            feats[7] = f.x - ((float)c.w * VXc + XOFFc);
            feats[8] = f.y - ((float)c.z * VYc + YOFFc);
            feats[9] = f.z - ((float)c.y * VZc + ZOFFc);
            feats[10] = sqrtf(f.x * f.x + f.y * f.y + f.z * f.z);
        } else {
#pragma unroll
            for (int k = 0; k < C_IN; k++) feats[k] = 0.0f;
        }
#pragma unroll
        for (int k = 0; k < C_IN; k++) sA[k * 128 + t] = feats[k];
        sIdx[t] = idx;
    }
    __syncthreads();

    // ---- tiled GEMM1 (K=11): acc tile = feats_tile @ W1 ----
    unsigned long long acc[32];
#pragma unroll
    for (int q = 0; q < 32; q++) acc[q] = 0ull;
    {
        const float* aBase  = sA + ty * 8;
        const float* bBase0 = sW1b + tx * 4;
        const float* bBase1 = sW1b + 32 + tx * 4;
#pragma unroll
        for (int k = 0; k < C_IN; k++) {
            float4 a0 = *reinterpret_cast<const float4*>(aBase + k * 128);
            float4 a1 = *reinterpret_cast<const float4*>(aBase + k * 128 + 4);
            ulonglong2 b01 = *reinterpret_cast<const ulonglong2*>(bBase0 + k * C_H);
            ulonglong2 b23 = *reinterpret_cast<const ulonglong2*>(bBase1 + k * C_H);
            unsigned long long bb[4] = { b01.x, b01.y, b23.x, b23.y };
            tile_fma(a0, a1, bb, acc);
        }
    }

    // ---- affine1 + relu -> pf tile (pf[mi*8+cc]) ----
    float pf[64];
#pragma unroll
    for (int q = 0; q < 4; q++) {
        int c0 = (q < 2) ? (4 * tx + 2 * q) : (32 + 4 * tx + 2 * (q - 2));
        float s0 = sSc[c0], s1 = sSc[c0 + 1];
        float h0 = sSh[c0], h1 = sSh[c0 + 1];
        int cc = (q < 2) ? 2 * q : 4 + 2 * (q - 2);
#pragma unroll
        for (int mi = 0; mi < 8; mi++) {
            float2 a = unpack2(acc[mi * 4 + q]);
            pf[mi * 8 + cc + 0] = fmaxf(fmaf(a.x, s0, h0), 0.0f);
            pf[mi * 8 + cc + 1] = fmaxf(fmaf(a.y, s1, h1), 0.0f);
        }
    }
    __syncthreads();   // all GEMM1 reads of sA(feats) done before transpose overwrite

    // ---- transpose pf tile into sA[k][p] with XOR swizzle (chunk c -> c ^ ((k>>2)&7) = c ^ tx) ----
#pragma unroll
    for (int cc = 0; cc < 8; cc++) {
        int k = colof(tx, cc);
        float4 lo = make_float4(pf[0 * 8 + cc], pf[1 * 8 + cc], pf[2 * 8 + cc], pf[3 * 8 + cc]);
        float4 hi = make_float4(pf[4 * 8 + cc], pf[5 * 8 + cc], pf[6 * 8 + cc], pf[7 * 8 + cc]);
        *reinterpret_cast<float4*>(sA + k * 128 + (((2 * ty) ^ tx) << 2))     = lo;
        *reinterpret_cast<float4*>(sA + k * 128 + (((2 * ty + 1) ^ tx) << 2)) = hi;
    }

    // ---- vmax1 atomics (tile layout) ----
#pragma unroll 1
    for (int mi = 0; mi < 8; mi++) {
        int vidx = sIdx[ty * 8 + mi];
        if (vidx < 0) continue;
        float* vb = g_vmax1 + (size_t)vidx * C_H;
#pragma unroll
        for (int cc = 0; cc < 8; cc++) {
            float v = pf[mi * 8 + cc];
            if (v > 0.0f) atomicMax((int*)&vb[colof(tx, cc)], __float_as_int(v));
        }
    }
    __syncthreads();

    // ---- tiled GEMM2a (K=64, swizzled A): acc = pf_tile @ (W2a*sc2) ----
#pragma unroll
    for (int q = 0; q < 32; q++) acc[q] = 0ull;
    {
        const float* bBase0 = sB + tx * 4;
        const float* bBase1 = sB + 32 + tx * 4;
#pragma unroll 4
        for (int k = 0; k < 64; k++) {
            int key = (k >> 2) & 7;
            int c0 = (2 * ty) ^ key;
            float4 a0 = *reinterpret_cast<const float4*>(sA + k * 128 + (c0 << 2));
            float4 a1 = *reinterpret_cast<const float4*>(sA + k * 128 + ((c0 ^ 1) << 2));
            ulonglong2 b01 = *reinterpret_cast<const ulonglong2*>(bBase0 + k * C_H);
            ulonglong2 b23 = *reinterpret_cast<const ulonglong2*>(bBase1 + k * C_H);
            unsigned long long bb[4] = { b01.x, b01.y, b23.x, b23.y };
            tile_fma(a0, a1, bb, acc);
        }
    }

    // ---- store c1' tile row-major ----
    int nvalid = n - bstart; if (nvalid > 128) nvalid = 128;
#pragma unroll
    for (int mi = 0; mi < 8; mi++) {
        int p = ty * 8 + mi;
        if (p >= nvalid) continue;
        float* r = g_ctr1 + (size_t)(bstart + p) * C_H;
        float2 a0 = unpack2(acc[mi * 4 + 0]);
        float2 a1 = unpack2(acc[mi * 4 + 1]);
        float2 a2 = unpack2(acc[mi * 4 + 2]);
        float2 a3 = unpack2(acc[mi * 4 + 3]);
        *reinterpret_cast<float4*>(r + 4 * tx)      = make_float4(a0.x, a0.y, a1.x, a1.y);
        *reinterpret_cast<float4*>(r + 32 + 4 * tx) = make_float4(a2.x, a2.y, a3.x, a3.y);
    }
}

// ---------------- K3: c2' = vmax1 @ (W2b*sc2) + shift2  (per voxel) ----------------
__global__ void __launch_bounds__(128)
k_ctr2(const float* __restrict__ W2, const float* __restrict__ scale2,
       const float* __restrict__ shift2)
{
    extern __shared__ float sm[];
    float* sA  = sm;                   // [64][AROW]
    float* sB  = sm + 64 * AROW;       // [64][64] W2b * scale2
    float* sSh = sB + 64 * C_H;

    const int t = threadIdx.x;
    const size_t v0 = (size_t)blockIdx.x * 128;

    for (int v = t; v < 64 * C_H; v += 128) sB[v] = W2[C_H * C_H + v] * scale2[v & 63];
    if (t < C_H) sSh[t] = shift2[t];

    const float4* vm4 = reinterpret_cast<const float4*>(g_vmax1 + (v0 + t) * C_H);
#pragma unroll
    for (int g = 0; g < 16; g++) {
        float4 x = vm4[g];
        int k0 = 4 * g;
        sA[(k0 + 0) * AROW + t] = x.x;
        sA[(k0 + 1) * AROW + t] = x.y;
        sA[(k0 + 2) * AROW + t] = x.z;
        sA[(k0 + 3) * AROW + t] = x.w;
    }
    __syncthreads();

    const int tx = t & 7;
    const int ty = t >> 3;
    unsigned long long acc[32];
#pragma unroll
    for (int q = 0; q < 32; q++) acc[q] = 0ull;

    {
        const float* aBase  = sA + ty * 8;
        const float* bBase0 = sB + tx * 4;
        const float* bBase1 = sB + 32 + tx * 4;
#pragma unroll 4
        for (int k = 0; k < 64; k++) {
            float4 a0 = *reinterpret_cast<const float4*>(aBase + k * AROW);
            float4 a1 = *reinterpret_cast<const float4*>(aBase + k * AROW + 4);
            ulonglong2 b01 = *reinterpret_cast<const ulonglong2*>(bBase0 + k * C_H);
            ulonglong2 b23 = *reinterpret_cast<const ulonglong2*>(bBase1 + k * C_H);
            unsigned long long bb[4] = { b01.x, b01.y, b23.x, b23.y };
            tile_fma(a0, a1, bb, acc);
        }
    }

    float4 sh0 = *reinterpret_cast<const float4*>(sSh + 4 * tx);
    float4 sh1 = *reinterpret_cast<const float4*>(sSh + 32 + 4 * tx);
#pragma unroll
    for (int mi = 0; mi < 8; mi++) {
        float* r = g_ctr2 + (v0 + ty * 8 + mi) * C_H;
        float2 a0 = unpack2(acc[mi * 4 + 0]);
        float2 a1 = unpack2(acc[mi * 4 + 1]);
        float2 a2 = unpack2(acc[mi * 4 + 2]);
        float2 a3 = unpack2(acc[mi * 4 + 3]);
        *reinterpret_cast<float4*>(r + 4 * tx) =
            make_float4(a0.x + sh0.x, a0.y + sh0.y, a1.x + sh0.z, a1.y + sh0.w);
        *reinterpret_cast<float4*>(r + 32 + 4 * tx) =
            make_float4(a2.x + sh1.x, a2.y + sh1.y, a3.x + sh1.z, a3.y + sh1.w);
    }
}

// ---------------- K4: out = segmax relu(c1' + c2'[idx]) ----------------
__global__ void __launch_bounds__(256)
k_final(const int* __restrict__ coors, float* __restrict__ out, int n)
{
    int gid = blockIdx.x * 256 + threadIdx.x;
    int i = gid >> 2;
    int q = gid & 3;
    if (i >= n) return;

    int4 c = reinterpret_cast<const int4*>(coors)[i];
    int idx = ((c.x * CZd + c.y) * CYd + c.z) * CXd + c.w;

    const float4* c1 = reinterpret_cast<const float4*>(g_ctr1 + (size_t)i * C_H) + q * 4;
    const float4* c2 = reinterpret_cast<const float4*>(g_ctr2 + (size_t)idx * C_H) + q * 4;
    float* ob = out + (size_t)idx * C_H + q * 16;

#pragma unroll
    for (int r = 0; r < 4; r++) {
        float4 a = c1[r];
        float4 b = c2[r];
        float v0 = fmaxf(a.x + b.x, 0.0f);
        float v1 = fmaxf(a.y + b.y, 0.0f);
        float v2 = fmaxf(a.z + b.z, 0.0f);
        float v3 = fmaxf(a.w + b.w, 0.0f);
        if (v0 > 0.0f) atomicMax((int*)&ob[4 * r + 0], __float_as_int(v0));
        if (v1 > 0.0f) atomicMax((int*)&ob[4 * r + 1], __float_as_int(v1));
        if (v2 > 0.0f) atomicMax((int*)&ob[4 * r + 2], __float_as_int(v2));
        if (v3 > 0.0f) atomicMax((int*)&ob[4 * r + 3], __float_as_int(v3));
    }
}

// ---------------- launch ----------------
extern "C" void kernel_launch(void* const* d_in, const int* in_sizes, int n_in,
                              void* d_out, int out_size)
{
    const float* features = (const float*)d_in[0];
    const int*   coors    = (const int*)d_in[1];
    const float* W1       = (const float*)d_in[2];
    const float* scale1   = (const float*)d_in[3];
    const float* shift1   = (const float*)d_in[4];
    const float* W2       = (const float*)d_in[5];
    const float* scale2   = (const float*)d_in[6];
    const float* shift2   = (const float*)d_in[7];
    float* out = (float*)d_out;

    int n = in_sizes[0] / 4;

    const int smemA = (64 * 128 + 64 * C_H + C_IN * C_H + 2 * C_H) * 4 + 128 * 4; // ~52KB
    const int smemB = (64 * AROW + 64 * C_H + C_H) * 4;                           // ~49.5KB
    static bool attr_set = false;
    if (!attr_set) {
        cudaFuncSetAttribute(k_fused1, cudaFuncAttributeMaxDynamicSharedMemorySize, smemA);
        cudaFuncSetAttribute(k_ctr2,   cudaFuncAttributeMaxDynamicSharedMemorySize, smemB);
        attr_set = true;
    }

    k_zero<<<592, 256>>>(out);
    k_sums<<<(n + 255) / 256, 256>>>(features, coors, n);
    k_fused1<<<(n + 127) / 128, 128, smemA>>>(features, coors, W1, scale1, shift1,
                                              W2, scale2, n);
    k_ctr2<<<CL / 128, 128, smemB>>>(W2, scale2, shift2);
    k_final<<<(4 * n + 255) / 256, 256>>>(coors, out, n);
}

// round 8
// speedup vs baseline: 1.5837x; 1.0782x over previous
#include <cuda_runtime.h>
#include <cstdint>

// ---------------- problem constants ----------------
#define NPTS_MAX 500000
#define BATCH 2
#define CZd 1
#define CYd 400
#define CXd 352
#define CL (BATCH * CZd * CYd * CXd)   // 281600 = 550*512
#define C_H 64
#define C_IN 11
#define AROW 132

__device__ __constant__ float VXc = 0.2f, VYc = 0.2f, VZc = 4.0f;
__device__ __constant__ float XOFFc = 0.1f;
__device__ __constant__ float YOFFc = -39.9f;
__device__ __constant__ float ZOFFc = -1.0f;

// ---------------- scratch ----------------
__device__ float g_ctr1[(size_t)C_H * NPTS_MAX];   // [rank][64]  c1' = pf1 @ (W2a*sc2)
__device__ float g_ctr2[(size_t)CL * C_H];         // [CL][64]    c2' = vmax @ (W2b*sc2) + sh2
__device__ float g_vmax1[(size_t)CL * C_H];
__device__ float g_vsum[(size_t)CL * 3];
__device__ int   g_cnt[CL];
__device__ int   g_off[CL];        // CSR start
__device__ int   g_off2[CL];       // scatter cursor
__device__ int   g_pidx[NPTS_MAX]; // voxel idx per point
__device__ int   g_sorted[NPTS_MAX]; // rank -> point id
__device__ int   g_bsum[1024];
__device__ int   g_bscan[1024];

// ---------------- f32x2 helpers ----------------
__device__ __forceinline__ unsigned long long dup2(float x)
{
    unsigned long long r;
    unsigned int xi = __float_as_uint(x);
    asm("mov.b64 %0, {%1, %1};" : "=l"(r) : "r"(xi));
    return r;
}
__device__ __forceinline__ void ffma2(unsigned long long& acc,
                                      unsigned long long a, unsigned long long b)
{
    asm("fma.rn.f32x2 %0, %1, %2, %0;" : "+l"(acc) : "l"(a), "l"(b));
}
__device__ __forceinline__ float2 unpack2(unsigned long long v)
{
    unsigned int lo, hi;
    asm("mov.b64 {%0, %1}, %2;" : "=r"(lo), "=r"(hi) : "l"(v));
    return make_float2(__uint_as_float(lo), __uint_as_float(hi));
}
__device__ __forceinline__ int colof(int tx, int cc)
{
    return (cc < 4) ? (4 * tx + cc) : (32 + 4 * tx + cc - 4);
}
__device__ __forceinline__ void tile_fma(const float4 a0, const float4 a1,
                                         const unsigned long long bb[4],
                                         unsigned long long acc[32])
{
    float av[8] = { a0.x, a0.y, a0.z, a0.w, a1.x, a1.y, a1.z, a1.w };
#pragma unroll
    for (int mi = 0; mi < 8; mi++) {
        unsigned long long am = dup2(av[mi]);
#pragma unroll
        for (int q = 0; q < 4; q++) ffma2(acc[mi * 4 + q], am, bb[q]);
    }
}

// ---------------- K0: zero vmax/vsum/cnt (NOT out) ----------------
__global__ void k_zero()
{
    const int total = CL * C_H;
    for (int i = blockIdx.x * blockDim.x + threadIdx.x; i < total;
         i += gridDim.x * blockDim.x) {
        g_vmax1[i] = 0.0f;
        if (i < CL * 3) g_vsum[i] = 0.0f;
        if (i < CL)     g_cnt[i] = 0;
    }
}

// ---------------- K1: count + cache idx ----------------
__global__ void k_count(const int* __restrict__ coors, int n)
{
    int i = blockIdx.x * blockDim.x + threadIdx.x;
    if (i >= n) return;
    int4 c = reinterpret_cast<const int4*>(coors)[i];
    int idx = ((c.x * CZd + c.y) * CYd + c.z) * CXd + c.w;
    g_pidx[i] = idx;
    atomicAdd(&g_cnt[idx], 1);
}

// ---------------- scan: 3 phases over CL = 550*512 ----------------
__device__ __forceinline__ int warp_incl_scan(int v)
{
    int s = v;
#pragma unroll
    for (int d = 1; d < 32; d <<= 1) {
        int t = __shfl_up_sync(0xffffffffu, s, d);
        if ((threadIdx.x & 31) >= d) s += t;
    }
    return s;
}

__global__ void k_scanA()
{
    __shared__ int ws[16];
    int g = blockIdx.x * 512 + threadIdx.x;
    int lane = threadIdx.x & 31, wid = threadIdx.x >> 5;
    int v = g_cnt[g];
    int s = warp_incl_scan(v);
    if (lane == 31) ws[wid] = s;
    __syncthreads();
    if (wid == 0) {
        int t = (lane < 16) ? ws[lane] : 0;
#pragma unroll
        for (int d = 1; d < 16; d <<= 1) {
            int u = __shfl_up_sync(0xffffffffu, t, d);
            if (lane >= d) t += u;
        }
        if (lane < 16) ws[lane] = t;
    }
    __syncthreads();
    int base = (wid > 0) ? ws[wid - 1] : 0;
    g_off[g] = base + s - v;               // block-local exclusive
    if (threadIdx.x == 511) g_bsum[blockIdx.x] = base + s;
}

__global__ void k_scanB()
{
    __shared__ int ws[32];
    int t = threadIdx.x;                    // 1024 threads
    int lane = t & 31, wid = t >> 5;
    int v = (t < 550) ? g_bsum[t] : 0;
    int s = warp_incl_scan(v);
    if (lane == 31) ws[wid] = s;
    __syncthreads();
    if (wid == 0) {
        int u = ws[lane];
#pragma unroll
        for (int d = 1; d < 32; d <<= 1) {
            int w = __shfl_up_sync(0xffffffffu, u, d);
            if (lane >= d) u += w;
        }
        ws[lane] = u;
    }
    __syncthreads();
    int base = (wid > 0) ? ws[wid - 1] : 0;
    if (t < 550) g_bscan[t] = base + s - v;  // exclusive over block sums
}

__global__ void k_scanC()
{
    int g = blockIdx.x * 512 + threadIdx.x;
    int o = g_off[g] + g_bscan[blockIdx.x];
    g_off[g] = o;
    g_off2[g] = o;
}

// ---------------- scatter + vsum ----------------
__global__ void k_scatter(const float* __restrict__ features, int n)
{
    int i = blockIdx.x * blockDim.x + threadIdx.x;
    if (i >= n) return;
    int idx = g_pidx[i];
    int r = atomicAdd(&g_off2[idx], 1);
    g_sorted[r] = i;
    float4 f = reinterpret_cast<const float4*>(features)[i];
    atomicAdd(&g_vsum[3 * idx + 0], f.x);
    atomicAdd(&g_vsum[3 * idx + 1], f.y);
    atomicAdd(&g_vsum[3 * idx + 2], f.z);
}

// ---------------- K2: fused GEMM1 + vmax (run-dedup) + GEMM2a, rank order ----------------
__global__ void __launch_bounds__(128, 4)
k_fused1(const float* __restrict__ features, const int* __restrict__ coors,
         const float* __restrict__ W1, const float* __restrict__ scale1,
         const float* __restrict__ shift1, const float* __restrict__ W2,
         const float* __restrict__ scale2, int n)
{
    extern __shared__ float sm[];
    float* sA   = sm;                      // [64][128] feats then swizzled pf
    float* sB   = sA + 64 * 128;           // [64][64]  W2a * scale2
    float* sW1b = sB + 64 * C_H;           // [11][64]
    float* sSc  = sW1b + C_IN * C_H;
    float* sSh  = sSc + C_H;
    int*   sIdx = (int*)(sSh + C_H);       // 128

    const int t = threadIdx.x;
    const int tx = t & 7;
    const int ty = t >> 3;
    const int bstart = blockIdx.x * 128;
    const int r = bstart + t;              // rank

    for (int v = t; v < 64 * C_H; v += 128) sB[v] = W2[v] * scale2[v & 63];
    for (int v = t; v < C_IN * C_H; v += 128) sW1b[v] = W1[v];
    if (t < C_H) { sSc[t] = scale1[t]; sSh[t] = shift1[t]; }

    // ---- per-thread feats (gather by rank) ----
    int idx = -1;
    {
        float feats[C_IN];
        if (r < n) {
            int j = g_sorted[r];
            idx = g_pidx[j];
            int4 c = reinterpret_cast<const int4*>(coors)[j];
            float4 f = reinterpret_cast<const float4*>(features)[j];
            float inv = 1.0f / fmaxf((float)g_cnt[idx], 1.0f);
            float mx = g_vsum[3 * idx + 0] * inv;
            float my = g_vsum[3 * idx + 1] * inv;
            float mz = g_vsum[3 * idx + 2] * inv;
            feats[0] = f.x; feats[1] = f.y; feats[2] = f.z; feats[3] = f.w;
            feats[4] = f.x - mx; feats[5] = f.y - my; feats[6] = f.z - mz;
            feats[7] = f.x - ((float)c.w * VXc + XOFFc);
            feats[8] = f.y - ((float)c.z * VYc + YOFFc);
            feats[9] = f.z - ((float)c.y * VZc + ZOFFc);
            feats[10] = sqrtf(f.x * f.x + f.y * f.y + f.z * f.z);
        } else {
#pragma unroll
            for (int k = 0; k < C_IN; k++) feats[k] = 0.0f;
        }
#pragma unroll
        for (int k = 0; k < C_IN; k++) sA[k * 128 + t] = feats[k];
        sIdx[t] = idx;
    }
    __syncthreads();

    // ---- tiled GEMM1 (K=11) ----
    unsigned long long acc[32];
#pragma unroll
    for (int q = 0; q < 32; q++) acc[q] = 0ull;
    {
        const float* aBase  = sA + ty * 8;
        const float* bBase0 = sW1b + tx * 4;
        const float* bBase1 = sW1b + 32 + tx * 4;
#pragma unroll
        for (int k = 0; k < C_IN; k++) {
            float4 a0 = *reinterpret_cast<const float4*>(aBase + k * 128);
            float4 a1 = *reinterpret_cast<const float4*>(aBase + k * 128 + 4);
            ulonglong2 b01 = *reinterpret_cast<const ulonglong2*>(bBase0 + k * C_H);
            ulonglong2 b23 = *reinterpret_cast<const ulonglong2*>(bBase1 + k * C_H);
            unsigned long long bb[4] = { b01.x, b01.y, b23.x, b23.y };
            tile_fma(a0, a1, bb, acc);
        }
    }

    // ---- affine1 + relu -> pf tile ----
    float pf[64];
#pragma unroll
    for (int q = 0; q < 4; q++) {
        int c0 = (q < 2) ? (4 * tx + 2 * q) : (32 + 4 * tx + 2 * (q - 2));
        float s0 = sSc[c0], s1 = sSc[c0 + 1];
        float h0 = sSh[c0], h1 = sSh[c0 + 1];
        int cc = (q < 2) ? 2 * q : 4 + 2 * (q - 2);
#pragma unroll
        for (int mi = 0; mi < 8; mi++) {
            float2 a = unpack2(acc[mi * 4 + q]);
            pf[mi * 8 + cc + 0] = fmaxf(fmaf(a.x, s0, h0), 0.0f);
            pf[mi * 8 + cc + 1] = fmaxf(fmaf(a.y, s1, h1), 0.0f);
        }
    }
    __syncthreads();

    // ---- transpose pf into sA[k][p], XOR swizzle ----
#pragma unroll
    for (int cc = 0; cc < 8; cc++) {
        int k = colof(tx, cc);
        float4 lo = make_float4(pf[0 * 8 + cc], pf[1 * 8 + cc], pf[2 * 8 + cc], pf[3 * 8 + cc]);
        float4 hi = make_float4(pf[4 * 8 + cc], pf[5 * 8 + cc], pf[6 * 8 + cc], pf[7 * 8 + cc]);
        *reinterpret_cast<float4*>(sA + k * 128 + (((2 * ty) ^ tx) << 2))     = lo;
        *reinterpret_cast<float4*>(sA + k * 128 + (((2 * ty + 1) ^ tx) << 2)) = hi;
    }

    // ---- vmax atomics with sorted-run dedup ----
    {
        int prev = -1;
        float vm[8];
#pragma unroll 1
        for (int mi = 0; mi < 8; mi++) {
            int vidx = sIdx[ty * 8 + mi];
            if (vidx != prev) {
                if (prev >= 0) {
                    float* vb = g_vmax1 + (size_t)prev * C_H;
#pragma unroll
                    for (int cc = 0; cc < 8; cc++)
                        if (vm[cc] > 0.0f)
                            atomicMax((int*)&vb[colof(tx, cc)], __float_as_int(vm[cc]));
                }
                prev = vidx;
#pragma unroll
                for (int cc = 0; cc < 8; cc++) vm[cc] = pf[mi * 8 + cc];
            } else {
#pragma unroll
                for (int cc = 0; cc < 8; cc++) vm[cc] = fmaxf(vm[cc], pf[mi * 8 + cc]);
            }
        }
        if (prev >= 0) {
            float* vb = g_vmax1 + (size_t)prev * C_H;
#pragma unroll
            for (int cc = 0; cc < 8; cc++)
                if (vm[cc] > 0.0f)
                    atomicMax((int*)&vb[colof(tx, cc)], __float_as_int(vm[cc]));
        }
    }
    __syncthreads();

    // ---- tiled GEMM2a (K=64, swizzled A) ----
#pragma unroll
    for (int q = 0; q < 32; q++) acc[q] = 0ull;
    {
        const float* bBase0 = sB + tx * 4;
        const float* bBase1 = sB + 32 + tx * 4;
#pragma unroll 4
        for (int k = 0; k < 64; k++) {
            int key = (k >> 2) & 7;
            int c0 = (2 * ty) ^ key;
            float4 a0 = *reinterpret_cast<const float4*>(sA + k * 128 + (c0 << 2));
            float4 a1 = *reinterpret_cast<const float4*>(sA + k * 128 + ((c0 ^ 1) << 2));
            ulonglong2 b01 = *reinterpret_cast<const ulonglong2*>(bBase0 + k * C_H);
            ulonglong2 b23 = *reinterpret_cast<const ulonglong2*>(bBase1 + k * C_H);
            unsigned long long bb[4] = { b01.x, b01.y, b23.x, b23.y };
            tile_fma(a0, a1, bb, acc);
        }
    }

    // ---- store c1' by rank ----
    int nvalid = n - bstart; if (nvalid > 128) nvalid = 128;
#pragma unroll
    for (int mi = 0; mi < 8; mi++) {
        int p = ty * 8 + mi;
        if (p >= nvalid) continue;
        float* rr = g_ctr1 + (size_t)(bstart + p) * C_H;
        float2 a0 = unpack2(acc[mi * 4 + 0]);
        float2 a1 = unpack2(acc[mi * 4 + 1]);
        float2 a2 = unpack2(acc[mi * 4 + 2]);
        float2 a3 = unpack2(acc[mi * 4 + 3]);
        *reinterpret_cast<float4*>(rr + 4 * tx)      = make_float4(a0.x, a0.y, a1.x, a1.y);
        *reinterpret_cast<float4*>(rr + 32 + 4 * tx) = make_float4(a2.x, a2.y, a3.x, a3.y);
    }
}

// ---------------- K3: c2' = vmax1 @ (W2b*sc2) + shift2 ----------------
__global__ void __launch_bounds__(128)
k_ctr2(const float* __restrict__ W2, const float* __restrict__ scale2,
       const float* __restrict__ shift2)
{
    extern __shared__ float sm[];
    float* sA  = sm;                   // [64][AROW]
    float* sB  = sm + 64 * AROW;       // [64][64]
    float* sSh = sB + 64 * C_H;

    const int t = threadIdx.x;
    const size_t v0 = (size_t)blockIdx.x * 128;

    for (int v = t; v < 64 * C_H; v += 128) sB[v] = W2[C_H * C_H + v] * scale2[v & 63];
    if (t < C_H) sSh[t] = shift2[t];

    const float4* vm4 = reinterpret_cast<const float4*>(g_vmax1 + (v0 + t) * C_H);
#pragma unroll
    for (int g = 0; g < 16; g++) {
        float4 x = vm4[g];
        int k0 = 4 * g;
        sA[(k0 + 0) * AROW + t] = x.x;
        sA[(k0 + 1) * AROW + t] = x.y;
        sA[(k0 + 2) * AROW + t] = x.z;
        sA[(k0 + 3) * AROW + t] = x.w;
    }
    __syncthreads();

    const int tx = t & 7;
    const int ty = t >> 3;
    unsigned long long acc[32];
#pragma unroll
    for (int q = 0; q < 32; q++) acc[q] = 0ull;
    {
        const float* aBase  = sA + ty * 8;
        const float* bBase0 = sB + tx * 4;
        const float* bBase1 = sB + 32 + tx * 4;
#pragma unroll 4
        for (int k = 0; k < 64; k++) {
            float4 a0 = *reinterpret_cast<const float4*>(aBase + k * AROW);
            float4 a1 = *reinterpret_cast<const float4*>(aBase + k * AROW + 4);
            ulonglong2 b01 = *reinterpret_cast<const ulonglong2*>(bBase0 + k * C_H);
            ulonglong2 b23 = *reinterpret_cast<const ulonglong2*>(bBase1 + k * C_H);
            unsigned long long bb[4] = { b01.x, b01.y, b23.x, b23.y };
            tile_fma(a0, a1, bb, acc);
        }
    }

    float4 sh0 = *reinterpret_cast<const float4*>(sSh + 4 * tx);
    float4 sh1 = *reinterpret_cast<const float4*>(sSh + 32 + 4 * tx);
#pragma unroll
    for (int mi = 0; mi < 8; mi++) {
        float* r = g_ctr2 + (v0 + ty * 8 + mi) * C_H;
        float2 a0 = unpack2(acc[mi * 4 + 0]);
        float2 a1 = unpack2(acc[mi * 4 + 1]);
        float2 a2 = unpack2(acc[mi * 4 + 2]);
        float2 a3 = unpack2(acc[mi * 4 + 3]);
        *reinterpret_cast<float4*>(r + 4 * tx) =
            make_float4(a0.x + sh0.x, a0.y + sh0.y, a1.x + sh0.z, a1.y + sh0.w);
        *reinterpret_cast<float4*>(r + 32 + 4 * tx) =
            make_float4(a2.x + sh1.x, a2.y + sh1.y, a3.x + sh1.z, a3.y + sh1.w);
    }
}

// ---------------- K4: voxel-centric final, no atomics ----------------
// warp per voxel: out[v] = max(0, max_{r in run} (c1'[r] + c2'[v])), 0 if empty
__global__ void __launch_bounds__(256)
k_final(float* __restrict__ out)
{
    int v = blockIdx.x * 8 + (threadIdx.x >> 5);
    int lane = threadIdx.x & 31;
    int cnt = g_cnt[v];
    float2 acc = make_float2(0.0f, 0.0f);
    if (cnt > 0) {
        int off = g_off[v];
        float2 b = reinterpret_cast<const float2*>(g_ctr2 + (size_t)v * C_H)[lane];
        for (int r = off; r < off + cnt; r++) {
            float2 a = reinterpret_cast<const float2*>(g_ctr1 + (size_t)r * C_H)[lane];
            acc.x = fmaxf(acc.x, a.x + b.x);
            acc.y = fmaxf(acc.y, a.y + b.y);
        }
    }
    reinterpret_cast<float2*>(out + (size_t)v * C_H)[lane] = acc;
}

// ---------------- launch ----------------
extern "C" void kernel_launch(void* const* d_in, const int* in_sizes, int n_in,
                              void* d_out, int out_size)
{
    const float* features = (const float*)d_in[0];
    const int*   coors    = (const int*)d_in[1];
    const float* W1       = (const float*)d_in[2];
    const float* scale1   = (const float*)d_in[3];
    const float* shift1   = (const float*)d_in[4];
    const float* W2       = (const float*)d_in[5];
    const float* scale2   = (const float*)d_in[6];
    const float* shift2   = (const float*)d_in[7];
    float* out = (float*)d_out;

    int n = in_sizes[0] / 4;

    const int smemA = (64 * 128 + 64 * C_H + C_IN * C_H + 2 * C_H) * 4 + 128 * 4;
    const int smemB = (64 * AROW + 64 * C_H + C_H) * 4;
    static bool attr_set = false;
    if (!attr_set) {
        cudaFuncSetAttribute(k_fused1, cudaFuncAttributeMaxDynamicSharedMemorySize, smemA);
        cudaFuncSetAttribute(k_ctr2,   cudaFuncAttributeMaxDynamicSharedMemorySize, smemB);
        attr_set = true;
    }

    k_zero<<<592, 256>>>();
    k_count<<<(n + 255) / 256, 256>>>(coors, n);
    k_scanA<<<550, 512>>>();
    k_scanB<<<1, 1024>>>();
    k_scanC<<<550, 512>>>();
    k_scatter<<<(n + 255) / 256, 256>>>(features, n);
    k_fused1<<<(n + 127) / 128, 128, smemA>>>(features, coors, W1, scale1, shift1,
                                              W2, scale2, n);
    k_ctr2<<<CL / 128, 128, smemB>>>(W2, scale2, shift2);
    k_final<<<CL / 8, 256>>>(out);
}

// round 9
// speedup vs baseline: 1.6019x; 1.0115x over previous
#include <cuda_runtime.h>
#include <cstdint>

// ---------------- problem constants ----------------
#define NPTS_MAX 500000
#define BATCH 2
#define CZd 1
#define CYd 400
#define CXd 352
#define CL (BATCH * CZd * CYd * CXd)   // 281600 = 550*512
#define C_H 64
#define C_IN 11
#define AROW 132

__device__ __constant__ float VXc = 0.2f, VYc = 0.2f, VZc = 4.0f;
__device__ __constant__ float XOFFc = 0.1f;
__device__ __constant__ float YOFFc = -39.9f;
__device__ __constant__ float ZOFFc = -1.0f;

// ---------------- scratch ----------------
__device__ float g_ctr1[(size_t)C_H * NPTS_MAX];   // [rank][64]
__device__ float g_ctr2[(size_t)CL * C_H];         // [CL][64]
__device__ float g_vmax1[(size_t)CL * C_H];
__device__ float g_vsum[(size_t)CL * 3];
__device__ int   g_cnt[CL];
__device__ int   g_off[CL];
__device__ int   g_off2[CL];
__device__ int   g_pidx[NPTS_MAX];
__device__ int   g_sorted[NPTS_MAX];
__device__ int   g_bsum[1024];
__device__ int   g_bscan[1024];

// ---------------- f32x2 helpers ----------------
__device__ __forceinline__ unsigned long long dup2(float x)
{
    unsigned long long r;
    unsigned int xi = __float_as_uint(x);
    asm("mov.b64 %0, {%1, %1};" : "=l"(r) : "r"(xi));
    return r;
}
__device__ __forceinline__ void ffma2(unsigned long long& acc,
                                      unsigned long long a, unsigned long long b)
{
    asm("fma.rn.f32x2 %0, %1, %2, %0;" : "+l"(acc) : "l"(a), "l"(b));
}
__device__ __forceinline__ float2 unpack2(unsigned long long v)
{
    unsigned int lo, hi;
    asm("mov.b64 {%0, %1}, %2;" : "=r"(lo), "=r"(hi) : "l"(v));
    return make_float2(__uint_as_float(lo), __uint_as_float(hi));
}
__device__ __forceinline__ int colof(int tx, int cc)
{
    return (cc < 4) ? (4 * tx + cc) : (32 + 4 * tx + cc - 4);
}
__device__ __forceinline__ void tile_fma(const float4 a0, const float4 a1,
                                         const unsigned long long bb0,
                                         const unsigned long long bb1,
                                         const unsigned long long bb2,
                                         const unsigned long long bb3,
                                         unsigned long long acc[32])
{
    float av[8] = { a0.x, a0.y, a0.z, a0.w, a1.x, a1.y, a1.z, a1.w };
#pragma unroll
    for (int mi = 0; mi < 8; mi++) {
        unsigned long long am = dup2(av[mi]);
        ffma2(acc[mi * 4 + 0], am, bb0);
        ffma2(acc[mi * 4 + 1], am, bb1);
        ffma2(acc[mi * 4 + 2], am, bb2);
        ffma2(acc[mi * 4 + 3], am, bb3);
    }
}

// ---------------- K0: zero vmax/vsum/cnt (vectorized) ----------------
__global__ void k_zero()
{
    const float4 z4 = make_float4(0.f, 0.f, 0.f, 0.f);
    float4* vm = reinterpret_cast<float4*>(g_vmax1);
    const int total4 = CL * C_H / 4;   // 4,505,600
    for (int i = blockIdx.x * blockDim.x + threadIdx.x; i < total4;
         i += gridDim.x * blockDim.x) {
        vm[i] = z4;
        if (i < CL) { g_cnt[i] = 0; }
        if (i < CL * 3) g_vsum[i] = 0.0f;
    }
}

// ---------------- K1: count + cache idx ----------------
__global__ void k_count(const int* __restrict__ coors, int n)
{
    int i = blockIdx.x * blockDim.x + threadIdx.x;
    if (i >= n) return;
    int4 c = reinterpret_cast<const int4*>(coors)[i];
    int idx = ((c.x * CZd + c.y) * CYd + c.z) * CXd + c.w;
    g_pidx[i] = idx;
    atomicAdd(&g_cnt[idx], 1);
}

// ---------------- scan over CL = 550*512 ----------------
__device__ __forceinline__ int warp_incl_scan(int v)
{
    int s = v;
#pragma unroll
    for (int d = 1; d < 32; d <<= 1) {
        int t = __shfl_up_sync(0xffffffffu, s, d);
        if ((threadIdx.x & 31) >= d) s += t;
    }
    return s;
}

__global__ void k_scanA()
{
    __shared__ int ws[16];
    int g = blockIdx.x * 512 + threadIdx.x;
    int lane = threadIdx.x & 31, wid = threadIdx.x >> 5;
    int v = g_cnt[g];
    int s = warp_incl_scan(v);
    if (lane == 31) ws[wid] = s;
    __syncthreads();
    if (wid == 0) {
        int t = (lane < 16) ? ws[lane] : 0;
#pragma unroll
        for (int d = 1; d < 16; d <<= 1) {
            int u = __shfl_up_sync(0xffffffffu, t, d);
            if (lane >= d) t += u;
        }
        if (lane < 16) ws[lane] = t;
    }
    __syncthreads();
    int base = (wid > 0) ? ws[wid - 1] : 0;
    g_off[g] = base + s - v;
    if (threadIdx.x == 511) g_bsum[blockIdx.x] = base + s;
}

__global__ void k_scanB()
{
    __shared__ int ws[32];
    int t = threadIdx.x;
    int lane = t & 31, wid = t >> 5;
    int v = (t < 550) ? g_bsum[t] : 0;
    int s = warp_incl_scan(v);
    if (lane == 31) ws[wid] = s;
    __syncthreads();
    if (wid == 0) {
        int u = ws[lane];
#pragma unroll
        for (int d = 1; d < 32; d <<= 1) {
            int w = __shfl_up_sync(0xffffffffu, u, d);
            if (lane >= d) u += w;
        }
        ws[lane] = u;
    }
    __syncthreads();
    int base = (wid > 0) ? ws[wid - 1] : 0;
    if (t < 550) g_bscan[t] = base + s - v;
}

__global__ void k_scanC()
{
    int g = blockIdx.x * 512 + threadIdx.x;
    int o = g_off[g] + g_bscan[blockIdx.x];
    g_off[g] = o;
    g_off2[g] = o;
}

// ---------------- scatter + vsum ----------------
__global__ void k_scatter(const float* __restrict__ features, int n)
{
    int i = blockIdx.x * blockDim.x + threadIdx.x;
    if (i >= n) return;
    int idx = g_pidx[i];
    int r = atomicAdd(&g_off2[idx], 1);
    g_sorted[r] = i;
    float4 f = reinterpret_cast<const float4*>(features)[i];
    atomicAdd(&g_vsum[3 * idx + 0], f.x);
    atomicAdd(&g_vsum[3 * idx + 1], f.y);
    atomicAdd(&g_vsum[3 * idx + 2], f.z);
}

// ---------------- K2: fused GEMM1 + vmax (run-dedup) + GEMM2a ----------------
__global__ void __launch_bounds__(128, 4)
k_fused1(const float* __restrict__ features, const int* __restrict__ coors,
         const float* __restrict__ W1, const float* __restrict__ scale1,
         const float* __restrict__ shift1, const float* __restrict__ W2,
         const float* __restrict__ scale2, int n)
{
    extern __shared__ float sm[];
    float* sA   = sm;                      // [64][128]
    float* sB   = sA + 64 * 128;           // [64][64]
    float* sW1b = sB + 64 * C_H;           // [11][64]
    float* sSc  = sW1b + C_IN * C_H;
    float* sSh  = sSc + C_H;
    int*   sIdx = (int*)(sSh + C_H);

    const int t = threadIdx.x;
    const int tx = t & 7;
    const int ty = t >> 3;
    const int bstart = blockIdx.x * 128;
    const int r = bstart + t;

    for (int v = t; v < 64 * C_H; v += 128) sB[v] = W2[v] * scale2[v & 63];
    for (int v = t; v < C_IN * C_H; v += 128) sW1b[v] = W1[v];
    if (t < C_H) { sSc[t] = scale1[t]; sSh[t] = shift1[t]; }

    int idx = -1;
    {
        float feats[C_IN];
        if (r < n) {
            int j = g_sorted[r];
            idx = g_pidx[j];
            int4 c = reinterpret_cast<const int4*>(coors)[j];
            float4 f = reinterpret_cast<const float4*>(features)[j];
            float inv = 1.0f / fmaxf((float)g_cnt[idx], 1.0f);
            float mx = g_vsum[3 * idx + 0] * inv;
            float my = g_vsum[3 * idx + 1] * inv;
            float mz = g_vsum[3 * idx + 2] * inv;
            feats[0] = f.x; feats[1] = f.y; feats[2] = f.z; feats[3] = f.w;
            feats[4] = f.x - mx; feats[5] = f.y - my; feats[6] = f.z - mz;
            feats[7] = f.x - ((float)c.w * VXc + XOFFc);
            feats[8] = f.y - ((float)c.z * VYc + YOFFc);
            feats[9] = f.z - ((float)c.y * VZc + ZOFFc);
            feats[10] = sqrtf(f.x * f.x + f.y * f.y + f.z * f.z);
        } else {
#pragma unroll
            for (int k = 0; k < C_IN; k++) feats[k] = 0.0f;
        }
#pragma unroll
        for (int k = 0; k < C_IN; k++) sA[k * 128 + t] = feats[k];
        sIdx[t] = idx;
    }
    __syncthreads();

    // ---- tiled GEMM1 (K=11) ----
    unsigned long long acc[32];
#pragma unroll
    for (int q = 0; q < 32; q++) acc[q] = 0ull;
    {
        const float* aBase  = sA + ty * 8;
        const float* bBase0 = sW1b + tx * 4;
        const float* bBase1 = sW1b + 32 + tx * 4;
#pragma unroll
        for (int k = 0; k < C_IN; k++) {
            float4 a0 = *reinterpret_cast<const float4*>(aBase + k * 128);
            float4 a1 = *reinterpret_cast<const float4*>(aBase + k * 128 + 4);
            ulonglong2 b01 = *reinterpret_cast<const ulonglong2*>(bBase0 + k * C_H);
            ulonglong2 b23 = *reinterpret_cast<const ulonglong2*>(bBase1 + k * C_H);
            tile_fma(a0, a1, b01.x, b01.y, b23.x, b23.y, acc);
        }
    }

    // ---- affine1 + relu -> pf tile ----
    float pf[64];
#pragma unroll
    for (int q = 0; q < 4; q++) {
        int c0 = (q < 2) ? (4 * tx + 2 * q) : (32 + 4 * tx + 2 * (q - 2));
        float s0 = sSc[c0], s1 = sSc[c0 + 1];
        float h0 = sSh[c0], h1 = sSh[c0 + 1];
        int cc = (q < 2) ? 2 * q : 4 + 2 * (q - 2);
#pragma unroll
        for (int mi = 0; mi < 8; mi++) {
            float2 a = unpack2(acc[mi * 4 + q]);
            pf[mi * 8 + cc + 0] = fmaxf(fmaf(a.x, s0, h0), 0.0f);
            pf[mi * 8 + cc + 1] = fmaxf(fmaf(a.y, s1, h1), 0.0f);
        }
    }
    __syncthreads();

    // ---- transpose pf into sA[k][p], XOR swizzle ----
#pragma unroll
    for (int cc = 0; cc < 8; cc++) {
        int k = colof(tx, cc);
        float4 lo = make_float4(pf[0 * 8 + cc], pf[1 * 8 + cc], pf[2 * 8 + cc], pf[3 * 8 + cc]);
        float4 hi = make_float4(pf[4 * 8 + cc], pf[5 * 8 + cc], pf[6 * 8 + cc], pf[7 * 8 + cc]);
        *reinterpret_cast<float4*>(sA + k * 128 + (((2 * ty) ^ tx) << 2))     = lo;
        *reinterpret_cast<float4*>(sA + k * 128 + (((2 * ty + 1) ^ tx) << 2)) = hi;
    }

    // ---- vmax atomics with sorted-run dedup ----
    {
        int prev = -1;
        float vm[8];
#pragma unroll 1
        for (int mi = 0; mi < 8; mi++) {
            int vidx = sIdx[ty * 8 + mi];
            if (vidx != prev) {
                if (prev >= 0) {
                    float* vb = g_vmax1 + (size_t)prev * C_H;
#pragma unroll
                    for (int cc = 0; cc < 8; cc++)
                        if (vm[cc] > 0.0f)
                            atomicMax((int*)&vb[colof(tx, cc)], __float_as_int(vm[cc]));
                }
                prev = vidx;
#pragma unroll
                for (int cc = 0; cc < 8; cc++) vm[cc] = pf[mi * 8 + cc];
            } else {
#pragma unroll
                for (int cc = 0; cc < 8; cc++) vm[cc] = fmaxf(vm[cc], pf[mi * 8 + cc]);
            }
        }
        if (prev >= 0) {
            float* vb = g_vmax1 + (size_t)prev * C_H;
#pragma unroll
            for (int cc = 0; cc < 8; cc++)
                if (vm[cc] > 0.0f)
                    atomicMax((int*)&vb[colof(tx, cc)], __float_as_int(vm[cc]));
        }
    }
    __syncthreads();

    // ---- tiled GEMM2a (K=64, swizzled A) with k+1 register prefetch ----
#pragma unroll
    for (int q = 0; q < 32; q++) acc[q] = 0ull;
    {
        const float* bBase0 = sB + tx * 4;
        const float* bBase1 = sB + 32 + tx * 4;
        int c0 = (2 * ty);                       // key(k=0)=0
        float4 a0c = *reinterpret_cast<const float4*>(sA + (c0 << 2));
        float4 a1c = *reinterpret_cast<const float4*>(sA + ((c0 ^ 1) << 2));
        ulonglong2 b01c = *reinterpret_cast<const ulonglong2*>(bBase0);
        ulonglong2 b23c = *reinterpret_cast<const ulonglong2*>(bBase1);
#pragma unroll 3
        for (int k = 0; k < 63; k++) {
            int kn = k + 1;
            int key = (kn >> 2) & 7;
            int cn = (2 * ty) ^ key;
            float4 a0n = *reinterpret_cast<const float4*>(sA + kn * 128 + (cn << 2));
            float4 a1n = *reinterpret_cast<const float4*>(sA + kn * 128 + ((cn ^ 1) << 2));
            ulonglong2 b01n = *reinterpret_cast<const ulonglong2*>(bBase0 + kn * C_H);
            ulonglong2 b23n = *reinterpret_cast<const ulonglong2*>(bBase1 + kn * C_H);
            tile_fma(a0c, a1c, b01c.x, b01c.y, b23c.x, b23c.y, acc);
            a0c = a0n; a1c = a1n; b01c = b01n; b23c = b23n;
        }
        tile_fma(a0c, a1c, b01c.x, b01c.y, b23c.x, b23c.y, acc);
    }

    // ---- store c1' by rank ----
    int nvalid = n - bstart; if (nvalid > 128) nvalid = 128;
#pragma unroll
    for (int mi = 0; mi < 8; mi++) {
        int p = ty * 8 + mi;
        if (p >= nvalid) continue;
        float* rr = g_ctr1 + (size_t)(bstart + p) * C_H;
        float2 a0 = unpack2(acc[mi * 4 + 0]);
        float2 a1 = unpack2(acc[mi * 4 + 1]);
        float2 a2 = unpack2(acc[mi * 4 + 2]);
        float2 a3 = unpack2(acc[mi * 4 + 3]);
        *reinterpret_cast<float4*>(rr + 4 * tx)      = make_float4(a0.x, a0.y, a1.x, a1.y);
        *reinterpret_cast<float4*>(rr + 32 + 4 * tx) = make_float4(a2.x, a2.y, a3.x, a3.y);
    }
}

// ---------------- K3: c2' = vmax1 @ (W2b*sc2) + shift2 ----------------
__global__ void __launch_bounds__(128, 4)
k_ctr2(const float* __restrict__ W2, const float* __restrict__ scale2,
       const float* __restrict__ shift2)
{
    extern __shared__ float sm[];
    float* sA  = sm;                   // [64][AROW]
    float* sB  = sm + 64 * AROW;       // [64][64]
    float* sSh = sB + 64 * C_H;

    const int t = threadIdx.x;
    const size_t v0 = (size_t)blockIdx.x * 128;

    for (int v = t; v < 64 * C_H; v += 128) sB[v] = W2[C_H * C_H + v] * scale2[v & 63];
    if (t < C_H) sSh[t] = shift2[t];

    const float4* vm4 = reinterpret_cast<const float4*>(g_vmax1 + (v0 + t) * C_H);
#pragma unroll
    for (int g = 0; g < 16; g++) {
        float4 x = vm4[g];
        int k0 = 4 * g;
        sA[(k0 + 0) * AROW + t] = x.x;
        sA[(k0 + 1) * AROW + t] = x.y;
        sA[(k0 + 2) * AROW + t] = x.z;
        sA[(k0 + 3) * AROW + t] = x.w;
    }
    __syncthreads();

    const int tx = t & 7;
    const int ty = t >> 3;
    unsigned long long acc[32];
#pragma unroll
    for (int q = 0; q < 32; q++) acc[q] = 0ull;
    {
        const float* aBase  = sA + ty * 8;
        const float* bBase0 = sB + tx * 4;
        const float* bBase1 = sB + 32 + tx * 4;
        float4 a0c = *reinterpret_cast<const float4*>(aBase);
        float4 a1c = *reinterpret_cast<const float4*>(aBase + 4);
        ulonglong2 b01c = *reinterpret_cast<const ulonglong2*>(bBase0);
        ulonglong2 b23c = *reinterpret_cast<const ulonglong2*>(bBase1);
#pragma unroll 3
        for (int k = 0; k < 63; k++) {
            int kn = k + 1;
            float4 a0n = *reinterpret_cast<const float4*>(aBase + kn * AROW);
            float4 a1n = *reinterpret_cast<const float4*>(aBase + kn * AROW + 4);
            ulonglong2 b01n = *reinterpret_cast<const ulonglong2*>(bBase0 + kn * C_H);
            ulonglong2 b23n = *reinterpret_cast<const ulonglong2*>(bBase1 + kn * C_H);
            tile_fma(a0c, a1c, b01c.x, b01c.y, b23c.x, b23c.y, acc);
            a0c = a0n; a1c = a1n; b01c = b01n; b23c = b23n;
        }
        tile_fma(a0c, a1c, b01c.x, b01c.y, b23c.x, b23c.y, acc);
    }

    float4 sh0 = *reinterpret_cast<const float4*>(sSh + 4 * tx);
    float4 sh1 = *reinterpret_cast<const float4*>(sSh + 32 + 4 * tx);
#pragma unroll
    for (int mi = 0; mi < 8; mi++) {
        float* r = g_ctr2 + (v0 + ty * 8 + mi) * C_H;
        float2 a0 = unpack2(acc[mi * 4 + 0]);
        float2 a1 = unpack2(acc[mi * 4 + 1]);
        float2 a2 = unpack2(acc[mi * 4 + 2]);
        float2 a3 = unpack2(acc[mi * 4 + 3]);
        *reinterpret_cast<float4*>(r + 4 * tx) =
            make_float4(a0.x + sh0.x, a0.y + sh0.y, a1.x + sh0.z, a1.y + sh0.w);
        *reinterpret_cast<float4*>(r + 32 + 4 * tx) =
            make_float4(a2.x + sh1.x, a2.y + sh1.y, a3.x + sh1.z, a3.y + sh1.w);
    }
}

// ---------------- K4: voxel-centric final, no atomics ----------------
__global__ void __launch_bounds__(256)
k_final(float* __restrict__ out)
{
    int v = blockIdx.x * 8 + (threadIdx.x >> 5);
    int lane = threadIdx.x & 31;
    int cnt = g_cnt[v];
    float2 acc0 = make_float2(0.0f, 0.0f);
    float2 acc1 = make_float2(0.0f, 0.0f);
    if (cnt > 0) {
        int off = g_off[v];
        int end = off + cnt;
        float2 b = reinterpret_cast<const float2*>(g_ctr2 + (size_t)v * C_H)[lane];
        int r = off;
        for (; r + 1 < end; r += 2) {
            float2 a0 = reinterpret_cast<const float2*>(g_ctr1 + (size_t)r * C_H)[lane];
            float2 a1 = reinterpret_cast<const float2*>(g_ctr1 + (size_t)(r + 1) * C_H)[lane];
            acc0.x = fmaxf(acc0.x, a0.x + b.x);
            acc0.y = fmaxf(acc0.y, a0.y + b.y);
            acc1.x = fmaxf(acc1.x, a1.x + b.x);
            acc1.y = fmaxf(acc1.y, a1.y + b.y);
        }
        if (r < end) {
            float2 a0 = reinterpret_cast<const float2*>(g_ctr1 + (size_t)r * C_H)[lane];
            acc0.x = fmaxf(acc0.x, a0.x + b.x);
            acc0.y = fmaxf(acc0.y, a0.y + b.y);
        }
        acc0.x = fmaxf(acc0.x, acc1.x);
        acc0.y = fmaxf(acc0.y, acc1.y);
    }
    reinterpret_cast<float2*>(out + (size_t)v * C_H)[lane] = acc0;
}

// ---------------- launch ----------------
extern "C" void kernel_launch(void* const* d_in, const int* in_sizes, int n_in,
                              void* d_out, int out_size)
{
    const float* features = (const float*)d_in[0];
    const int*   coors    = (const int*)d_in[1];
    const float* W1       = (const float*)d_in[2];
    const float* scale1   = (const float*)d_in[3];
    const float* shift1   = (const float*)d_in[4];
    const float* W2       = (const float*)d_in[5];
    const float* scale2   = (const float*)d_in[6];
    const float* shift2   = (const float*)d_in[7];
    float* out = (float*)d_out;

    int n = in_sizes[0] / 4;

    const int smemA = (64 * 128 + 64 * C_H + C_IN * C_H + 2 * C_H) * 4 + 128 * 4;
    const int smemB = (64 * AROW + 64 * C_H + C_H) * 4;
    static bool attr_set = false;
    if (!attr_set) {
        cudaFuncSetAttribute(k_fused1, cudaFuncAttributeMaxDynamicSharedMemorySize, smemA);
        cudaFuncSetAttribute(k_ctr2,   cudaFuncAttributeMaxDynamicSharedMemorySize, smemB);
        attr_set = true;
    }

    k_zero<<<1184, 256>>>();
    k_count<<<(n + 255) / 256, 256>>>(coors, n);
    k_scanA<<<550, 512>>>();
    k_scanB<<<1, 1024>>>();
    k_scanC<<<550, 512>>>();
    k_scatter<<<(n + 255) / 256, 256>>>(features, n);
    k_fused1<<<(n + 127) / 128, 128, smemA>>>(features, coors, W1, scale1, shift1,
                                              W2, scale2, n);
    k_ctr2<<<CL / 128, 128, smemB>>>(W2, scale2, shift2);
    k_final<<<CL / 8, 256>>>(out);
}